// round 8
// baseline (speedup 1.0000x reference)
#include <cuda_runtime.h>
#include <math.h>

typedef unsigned long long u64;

// Problem constants
#define Bq   32
#define Cc   128
#define Hh   64
#define Ww   64
#define WS   8
#define SHIFT 4
#define HEADS 4
#define HID  512
#define METAH 256
#define TOK  64
#define NWIN 64
#define DH   32

#define BT   512

// smem layout (floats)
#define OFF_A   0        // XT [128][66]  -> W2 stage (XW) -> F2T
#define OFF_B1  8448     // QT [128][66]  -> AO -> (tail of XW)
#define OFF_B2  16896    // KT [128][66]  -> PT -> HT
#define OFF_B3  25344    // VR [64][136]  -> ST [128][66]
#define OFF_S   34048    // weight stage (dbl-buf) / scores [4][64][66]
#define SM_FLOATS 50944  // total = 203776 bytes

__device__ float g_bias[HEADS * TOK * TOK];

// ---- packed f32x2 helpers --------------------------------------------------
__device__ __forceinline__ u64 pk(float lo, float hi) {
    u64 r; asm("mov.b64 %0,{%1,%2};" : "=l"(r) : "f"(lo), "f"(hi)); return r;
}
__device__ __forceinline__ void fma2(u64& d, u64 a, u64 b) {
    asm("fma.rn.f32x2 %0, %1, %2, %0;" : "+l"(d) : "l"(a), "l"(b));
}
__device__ __forceinline__ float2 upk(u64 v) {
    float2 f; asm("mov.b64 {%0,%1},%2;" : "=f"(f.x), "=f"(f.y) : "l"(v)); return f;
}

// ---- cp.async helpers -------------------------------------------------------
__device__ __forceinline__ void cpa16(void* sptr, const void* gptr) {
    unsigned s = (unsigned)__cvta_generic_to_shared(sptr);
    asm volatile("cp.async.cg.shared.global [%0], [%1], 16;" :: "r"(s), "l"(gptr));
}
#define CP_COMMIT() asm volatile("cp.async.commit_group;" ::: "memory")
#define CP_WAIT0()  asm volatile("cp.async.wait_group 0;"  ::: "memory")

// ---------------------------------------------------------------------------
// Kernel A: meta-network relative position bias (identical for all windows)
// ---------------------------------------------------------------------------
__global__ void bias_kernel(const float* __restrict__ w1, const float* __restrict__ b1,
                            const float* __restrict__ w2, const float* __restrict__ b2)
{
    int p = blockIdx.x * blockDim.x + threadIdx.x;
    if (p >= TOK * TOK) return;
    int i = p >> 6, j = p & 63;
    float d0 = (float)((i >> 3) - (j >> 3));
    float d1 = (float)((i & 7) - (j & 7));
    float r0 = copysignf(log1pf(fabsf(d0)), d0);
    float r1 = copysignf(log1pf(fabsf(d1)), d1);
    float a0 = b2[0], a1 = b2[1], a2 = b2[2], a3 = b2[3];
    for (int m = 0; m < METAH; ++m) {
        float h = fmaf(r0, w1[m], fmaf(r1, w1[METAH + m], b1[m]));
        h = fmaxf(h, 0.0f);
        float4 wv = *reinterpret_cast<const float4*>(w2 + m * 4);
        a0 = fmaf(h, wv.x, a0); a1 = fmaf(h, wv.y, a1);
        a2 = fmaf(h, wv.z, a2); a3 = fmaf(h, wv.w, a3);
    }
    g_bias[0 * 4096 + p] = a0; g_bias[1 * 4096 + p] = a1;
    g_bias[2 * 4096 + p] = a2; g_bias[3 * 4096 + p] = a3;
}

__device__ __forceinline__ int regid(int y) {
    return (y < Hh - WS) ? 0 : ((y < Hh - SHIFT) ? 1 : 2);
}

// Parallel LN stats over a [128][66] (feature-major) smem buffer.
__device__ __forceinline__ void ln_stats(const float* __restrict__ buf,
                                         float* __restrict__ s_mu,
                                         float* __restrict__ s_rs,
                                         int tid)
{
    int t = tid >> 3, l8 = tid & 7;
    float s = 0.f, s2 = 0.f;
    #pragma unroll
    for (int i = 0; i < 16; ++i) {
        float v = buf[(l8 + 8 * i) * 66 + t];
        s += v;
        s2 = fmaf(v, v, s2);
    }
    #pragma unroll
    for (int m = 4; m >= 1; m >>= 1) {
        s  += __shfl_xor_sync(0xffffffffu, s,  m);
        s2 += __shfl_xor_sync(0xffffffffu, s2, m);
    }
    if (l8 == 0) {
        float mu = s * (1.0f / Cc);
        float var = fmaf(-mu, mu, s2 * (1.0f / Cc));
        s_mu[t] = mu;
        s_rs[t] = rsqrtf(var + 1e-5f);
    }
}

// ---------------------------------------------------------------------------
// Kernel B: fused Swin V2 block, one CTA per (batch, window)
// ---------------------------------------------------------------------------
__global__ void __launch_bounds__(BT, 1)
swin_block_kernel(const float* __restrict__ x,
                  const float* __restrict__ qkv_w, const float* __restrict__ qkv_b,
                  const float* __restrict__ proj_w, const float* __restrict__ proj_b,
                  const float* __restrict__ tau,
                  const float* __restrict__ ln1_g, const float* __restrict__ ln1_b,
                  const float* __restrict__ ln2_g, const float* __restrict__ ln2_b,
                  const float* __restrict__ ffn_w1, const float* __restrict__ ffn_b1,
                  const float* __restrict__ ffn_w2, const float* __restrict__ ffn_b2,
                  float* __restrict__ out)
{
    extern __shared__ float sm[];
    float* XT = sm + OFF_A;    // [c][t] stride 66 ; later W2 stage, then F2T
    float* B1 = sm + OFF_B1;   // QT -> AO      [c][t] stride 66
    float* B2 = sm + OFF_B2;   // KT -> PT -> HT
    float* B3 = sm + OFF_B3;   // VR [k][c] stride 136 ; later ST [c][t] 66
    float* SS = sm + OFF_S;    // weight staging (dbl-buf) / scores S[h][ki][qi]

    __shared__ float s_qn[256], s_kn[256], s_mu[64], s_rs[64];

    const int tid = threadIdx.x;
    const int b  = blockIdx.x >> 6;
    const int wi = blockIdx.x & 63;
    const int wh = wi >> 3, ww = wi & 7;
    const float* xb = x + (size_t)b * Cc * Hh * Ww;

    float4* ssf4 = (float4*)SS;
    float4* xwf4 = (float4*)sm;                 // XT∪B1 region as flat stage
    const float4* qw4 = (const float4*)qkv_w;
    const float4* w14 = (const float4*)ffn_w1;
    const float4* w24 = (const float4*)ffn_w2;

    // ---- 1. gather shifted window, transposed: XT[c][t]
    for (int idx = tid; idx < TOK * Cc; idx += BT) {
        int c = idx >> 6, t = idx & 63;
        int py = (wh * WS + (t >> 3) + SHIFT) & 63;
        int px = (ww * WS + (t & 7) + SHIFT) & 63;
        XT[c * 66 + t] = xb[c * 4096 + py * 64 + px];
    }

    // ---- 2. QKV GEMM: XT[64x128] @ W[128x384]
    // 8 chunks of 16 c-rows, cp.async double-buffered in the two SS halves.
    {
        const int tt = tid >> 6, jt = tid & 63;
        const int t0 = tt * 8, j0 = jt * 6;
        u64 acc[4][6];
        #pragma unroll
        for (int j = 0; j < 6; ++j) {
            float bj = qkv_b[j0 + j];
            u64 bd = pk(bj, bj);
            #pragma unroll
            for (int p = 0; p < 4; ++p) acc[p][j] = bd;
        }
        // issue chunk 0 into buffer 0
        {
            float4* dst = ssf4;
            for (int i = tid; i < 1536; i += BT) {
                int r = i / 96, q = i - r * 96;
                cpa16(dst + i, qw4 + r * 96 + q);
            }
            CP_COMMIT();
        }
        for (int ci = 0; ci < 8; ++ci) {
            int cur = ci & 1;
            CP_WAIT0();
            __syncthreads();            // chunk ci ready; (ci=0: also gather barrier)
            if (ci < 7) {               // stream chunk ci+1 into the other half
                float4* dst = ssf4 + (1 - cur) * 1536;
                int c1 = (ci + 1) * 16;
                for (int i = tid; i < 1536; i += BT) {
                    int r = i / 96, q = i - r * 96;
                    cpa16(dst + i, qw4 + (c1 + r) * 96 + q);
                }
                CP_COMMIT();
            }
            const float* Wb = SS + cur * 6144;
            const int c0 = ci * 16;
            for (int cc = 0; cc < 16; ++cc) {
                const float* xr = XT + (c0 + cc) * 66 + t0;
                u64 xp0 = *(const u64*)(xr + 0);
                u64 xp1 = *(const u64*)(xr + 2);
                u64 xp2 = *(const u64*)(xr + 4);
                u64 xp3 = *(const u64*)(xr + 6);
                const float* wr = Wb + cc * 384 + j0;   // j0 even -> 8B aligned
                float2 w01 = *(const float2*)(wr + 0);
                float2 w23 = *(const float2*)(wr + 2);
                float2 w45 = *(const float2*)(wr + 4);
                float wj[6] = {w01.x, w01.y, w23.x, w23.y, w45.x, w45.y};
                #pragma unroll
                for (int j = 0; j < 6; ++j) {
                    u64 wd = pk(wj[j], wj[j]);
                    fma2(acc[0][j], xp0, wd);
                    fma2(acc[1][j], xp1, wd);
                    fma2(acc[2][j], xp2, wd);
                    fma2(acc[3][j], xp3, wd);
                }
            }
        }
        // write Q,K transposed [j][t]; V as [t][c] rows (for AV weight side)
        #pragma unroll
        for (int j = 0; j < 6; ++j) {
            int jg = j0 + j;
            #pragma unroll
            for (int p = 0; p < 4; ++p) {
                if (jg < 128) {
                    *(u64*)&B1[jg * 66 + t0 + 2 * p] = acc[p][j];
                } else if (jg < 256) {
                    *(u64*)&B2[(jg - 128) * 66 + t0 + 2 * p] = acc[p][j];
                } else {
                    float2 f = upk(acc[p][j]);
                    B3[(t0 + 2 * p)     * 136 + (jg - 256)] = f.x;
                    B3[(t0 + 2 * p + 1) * 136 + (jg - 256)] = f.y;
                }
            }
        }
    }
    __syncthreads();

    // ---- 3. q/k norms per (head, token); lane pair (tid, tid^1) splits DH
    {
        int r = tid >> 1, half = tid & 1;       // r = h*64 + t
        int h = r >> 6, t = r & 63;
        int d0 = half * 16;
        float sq = 0.f, sk = 0.f;
        #pragma unroll
        for (int d = 0; d < 16; ++d) {
            float qv = B1[(h * 32 + d0 + d) * 66 + t];
            float kv = B2[(h * 32 + d0 + d) * 66 + t];
            sq = fmaf(qv, qv, sq);
            sk = fmaf(kv, kv, sk);
        }
        sq += __shfl_xor_sync(0xffffffffu, sq, 1);
        sk += __shfl_xor_sync(0xffffffffu, sk, 1);
        if (half == 0) {
            s_qn[r] = sqrtf(sq);
            s_kn[r] = sqrtf(sk);
        }
    }
    __syncthreads();

    // ---- 4. scores -> SS as S[h][ki][qi] (stride 66)
    for (int it = tid; it < 1024; it += BT) {
        int h = it >> 8, qt = (it >> 4) & 15, kt = it & 15;
        int qi0 = qt * 4, ki0 = kt * 4;
        float tc = fmaxf(tau[h], 0.01f);
        float4 bq[4];
        #pragma unroll
        for (int p = 0; p < 4; ++p)
            bq[p] = *reinterpret_cast<const float4*>(
                        &g_bias[h * 4096 + (qi0 + p) * 64 + ki0]);
        u64 a0[4] = {0, 0, 0, 0}, a1[4] = {0, 0, 0, 0};
        for (int d = 0; d < DH; ++d) {
            int row = (h * 32 + d) * 66;
            u64 qp0 = *(const u64*)&B1[row + qi0];
            u64 qp1 = *(const u64*)&B1[row + qi0 + 2];
            float2 k01 = *(const float2*)&B2[row + ki0];
            float2 k23 = *(const float2*)&B2[row + ki0 + 2];
            u64 kd0 = pk(k01.x, k01.x), kd1 = pk(k01.y, k01.y);
            u64 kd2 = pk(k23.x, k23.x), kd3 = pk(k23.y, k23.y);
            fma2(a0[0], qp0, kd0); fma2(a1[0], qp1, kd0);
            fma2(a0[1], qp0, kd1); fma2(a1[1], qp1, kd1);
            fma2(a0[2], qp0, kd2); fma2(a1[2], qp1, kd2);
            fma2(a0[3], qp0, kd3); fma2(a1[3], qp1, kd3);
        }
        int rq[4], rk[4];
        #pragma unroll
        for (int i = 0; i < 4; ++i) {
            int qi = qi0 + i, ki = ki0 + i;
            rq[i] = regid(wh * WS + (qi >> 3)) * 3 + regid(ww * WS + (qi & 7));
            rk[i] = regid(wh * WS + (ki >> 3)) * 3 + regid(ww * WS + (ki & 7));
        }
        #pragma unroll
        for (int j = 0; j < 4; ++j) {
            float knv = s_kn[h * 64 + ki0 + j];
            float2 v0 = upk(a0[j]), v1 = upk(a1[j]);
            float o[4] = {v0.x, v0.y, v1.x, v1.y};
            #pragma unroll
            for (int p = 0; p < 4; ++p) {
                int qi = qi0 + p;
                float bias = (j == 0) ? bq[p].x : (j == 1) ? bq[p].y
                           : (j == 2) ? bq[p].z : bq[p].w;
                float sc = o[p] / fmaxf(s_qn[h * 64 + qi] * knv * tc, 1e-6f * tc)
                         + bias;
                if (rq[p] != rk[j]) sc -= 100.0f;
                o[p] = sc;
            }
            *(u64*)&SS[h * 4224 + (ki0 + j) * 66 + qi0]     = pk(o[0], o[1]);
            *(u64*)&SS[h * 4224 + (ki0 + j) * 66 + qi0 + 2] = pk(o[2], o[3]);
        }
    }
    __syncthreads();

    // ---- 5. softmax per (h, qi); lane pair (tid, tid^1) splits the 64 ki's
    {
        int r = tid >> 1, half = tid & 1;       // r = h*64 + qi
        int h = r >> 6, qi = r & 63;
        float* base = SS + h * 4224 + qi + half * 32 * 66;
        float mx = -1e30f;
        #pragma unroll 8
        for (int k = 0; k < 32; ++k) mx = fmaxf(mx, base[k * 66]);
        mx = fmaxf(mx, __shfl_xor_sync(0xffffffffu, mx, 1));
        float ssum = 0.f;
        #pragma unroll 8
        for (int k = 0; k < 32; ++k) {
            float e = __expf(base[k * 66] - mx);
            base[k * 66] = e;
            ssum += e;
        }
        ssum += __shfl_xor_sync(0xffffffffu, ssum, 1);
        float inv = 1.0f / ssum;
        #pragma unroll 8
        for (int k = 0; k < 32; ++k) base[k * 66] *= inv;
    }
    __syncthreads();

    // ---- 6. AV: out[t][c] = sum_k S[h][k][t] * VR[k][c] -> AO[c][t] (B1)
    // 8 t x 2 c per thread: halves dup-MOV cost vs 4x4 tile.
    {
        int tt = tid >> 6, ct = tid & 63;
        int t0 = tt * 8, c0 = ct * 2, h = c0 >> 5;
        const float* Sh = SS + h * 4224;
        u64 av[4][2] = {{0,0},{0,0},{0,0},{0,0}};
        for (int k = 0; k < TOK; ++k) {
            const float* sr = Sh + k * 66 + t0;
            u64 ap0 = *(const u64*)(sr + 0);
            u64 ap1 = *(const u64*)(sr + 2);
            u64 ap2 = *(const u64*)(sr + 4);
            u64 ap3 = *(const u64*)(sr + 6);
            float2 v = *(const float2*)&B3[k * 136 + c0];
            u64 vd0 = pk(v.x, v.x), vd1 = pk(v.y, v.y);
            fma2(av[0][0], ap0, vd0); fma2(av[0][1], ap0, vd1);
            fma2(av[1][0], ap1, vd0); fma2(av[1][1], ap1, vd1);
            fma2(av[2][0], ap2, vd0); fma2(av[2][1], ap2, vd1);
            fma2(av[3][0], ap3, vd0); fma2(av[3][1], ap3, vd1);
        }
        #pragma unroll
        for (int j = 0; j < 2; ++j)
            #pragma unroll
            for (int p = 0; p < 4; ++p)
                *(u64*)&B1[(c0 + j) * 66 + t0 + 2 * p] = av[p][j];
    }
    __syncthreads();

    // ---- 7. proj: AO @ proj_w -> PT[j][t] (B2); weights cp.async'd into SS
    {
        const float4* pw4 = (const float4*)proj_w;
        for (int i = tid; i < 4096; i += BT)
            cpa16(ssf4 + i, pw4 + i);
        CP_COMMIT(); CP_WAIT0();
    }
    __syncthreads();
    {
        int tt = tid >> 6, jt = tid & 63;
        int t0 = tt * 8, j0 = jt * 2;
        u64 pa[4][2];
        #pragma unroll
        for (int j = 0; j < 2; ++j) {
            float bj = proj_b[j0 + j];
            u64 bd = pk(bj, bj);
            #pragma unroll
            for (int p = 0; p < 4; ++p) pa[p][j] = bd;
        }
        for (int c = 0; c < Cc; ++c) {
            const float* xr = B1 + c * 66 + t0;
            u64 xp0 = *(const u64*)(xr + 0);
            u64 xp1 = *(const u64*)(xr + 2);
            u64 xp2 = *(const u64*)(xr + 4);
            u64 xp3 = *(const u64*)(xr + 6);
            float2 wp = *(const float2*)&SS[c * 128 + j0];   // j0 even -> aligned
            u64 wd0 = pk(wp.x, wp.x), wd1 = pk(wp.y, wp.y);
            fma2(pa[0][0], xp0, wd0); fma2(pa[0][1], xp0, wd1);
            fma2(pa[1][0], xp1, wd0); fma2(pa[1][1], xp1, wd1);
            fma2(pa[2][0], xp2, wd0); fma2(pa[2][1], xp2, wd1);
            fma2(pa[3][0], xp3, wd0); fma2(pa[3][1], xp3, wd1);
        }
        #pragma unroll
        for (int j = 0; j < 2; ++j)
            #pragma unroll
            for (int p = 0; p < 4; ++p)
                *(u64*)&B2[(j0 + j) * 66 + t0 + 2 * p] = pa[p][j];
    }
    __syncthreads();

    // SS is dead now until FFN1 -> start streaming W1 chunk 0 (overlaps LN1/skip)
    for (int i = tid; i < 4096; i += BT) {
        int r = i >> 5, q = i & 31;
        cpa16(ssf4 + i, w14 + r * 128 + q);
    }
    CP_COMMIT();

    // ---- 8. LN1 stats (over channels of PT, per token)
    ln_stats(B2, s_mu, s_rs, tid);
    __syncthreads();

    // ---- 9. skip ST[c][t] = XT + LN1(PT) -> B3
    for (int idx = tid; idx < TOK * Cc; idx += BT) {
        int c = idx >> 6, t = idx & 63;
        float v = (B2[c * 66 + t] - s_mu[t]) * s_rs[t] * ln1_g[c] + ln1_b[c];
        B3[c * 66 + t] = v + XT[c * 66 + t];
    }
    CP_WAIT0();
    __syncthreads();    // B3 ready AND W1(0) ready

    // ---- 10. FFN, hidden chunks of 128; FFN2 accs live in registers.
    // W2(kc) streams into XW (=XT∪B1, dead) during FFN1; W1(kc+1) into SS
    // during FFN2. 2 barriers per chunk.
    {
        int ftt = tid >> 6, fct = tid & 63;      // FFN2 tile: 8 t x 2 c
        int ft0 = ftt * 8, fc0 = fct * 2;
        u64 f2a[4][2];
        #pragma unroll
        for (int j = 0; j < 2; ++j) {
            float bb = ffn_b2[fc0 + j];
            u64 bd = pk(bb, bb);
            #pragma unroll
            for (int p = 0; p < 4; ++p) f2a[p][j] = bd;
        }
        int tt = tid >> 6, kt = tid & 63;
        int t0 = tt * 8, kk0 = kt * 2;

        for (int kc = 0; kc < 4; ++kc) {
            int k0 = kc * 128;
            // stream W2(kc) into XW while FFN1 computes
            for (int i = tid; i < 4096; i += BT) {
                int kk = i >> 5, q = i & 31;
                cpa16(xwf4 + i, w24 + (k0 + kk) * 32 + q);
            }
            CP_COMMIT();
            // FFN1: hidden = gelu(ST @ W1chunk + b1) -> HT[kk][t] (B2)
            u64 fa[4][2];
            #pragma unroll
            for (int j = 0; j < 2; ++j) {
                float bj = ffn_b1[k0 + kk0 + j];
                u64 bd = pk(bj, bj);
                #pragma unroll
                for (int p = 0; p < 4; ++p) fa[p][j] = bd;
            }
            for (int c = 0; c < Cc; ++c) {
                const float* xr = B3 + c * 66 + t0;
                u64 xp0 = *(const u64*)(xr + 0);
                u64 xp1 = *(const u64*)(xr + 2);
                u64 xp2 = *(const u64*)(xr + 4);
                u64 xp3 = *(const u64*)(xr + 6);
                float2 wp = *(const float2*)&SS[c * 128 + kk0];  // kk0 even -> aligned
                u64 wd0 = pk(wp.x, wp.x), wd1 = pk(wp.y, wp.y);
                fma2(fa[0][0], xp0, wd0); fma2(fa[0][1], xp0, wd1);
                fma2(fa[1][0], xp1, wd0); fma2(fa[1][1], xp1, wd1);
                fma2(fa[2][0], xp2, wd0); fma2(fa[2][1], xp2, wd1);
                fma2(fa[3][0], xp3, wd0); fma2(fa[3][1], xp3, wd1);
            }
            // B2(HT) write: safe — FFN2(kc-1) reads of B2 ended before the
            // final barrier of the previous iteration.
            #pragma unroll
            for (int j = 0; j < 2; ++j)
                #pragma unroll
                for (int p = 0; p < 4; ++p) {
                    float2 v = upk(fa[p][j]);
                    float g0 = 0.5f * v.x * (1.0f + erff(v.x * 0.70710678118654752f));
                    float g1 = 0.5f * v.y * (1.0f + erff(v.y * 0.70710678118654752f));
                    *(u64*)&B2[(kk0 + j) * 66 + t0 + 2 * p] = pk(g0, g1);
                }
            CP_WAIT0();
            __syncthreads();            // W2(kc) in XW + HT in B2 both ready
            // stream W1(kc+1) into SS while FFN2 computes (SS free: FFN1 done)
            if (kc < 3) {
                int k1 = (kc + 1) * 32;  // float4 col offset
                for (int i = tid; i < 4096; i += BT) {
                    int r = i >> 5, q = i & 31;
                    cpa16(ssf4 + i, w14 + r * 128 + k1 + q);
                }
                CP_COMMIT();
            }
            // FFN2 accumulate from XW (8 t x 2 c tile)
            for (int kk = 0; kk < 128; ++kk) {
                const float* hr = B2 + kk * 66 + ft0;
                u64 hp0 = *(const u64*)(hr + 0);
                u64 hp1 = *(const u64*)(hr + 2);
                u64 hp2 = *(const u64*)(hr + 4);
                u64 hp3 = *(const u64*)(hr + 6);
                float2 w = *(const float2*)&sm[kk * 128 + fc0];
                u64 wd0 = pk(w.x, w.x), wd1 = pk(w.y, w.y);
                fma2(f2a[0][0], hp0, wd0); fma2(f2a[0][1], hp0, wd1);
                fma2(f2a[1][0], hp1, wd0); fma2(f2a[1][1], hp1, wd1);
                fma2(f2a[2][0], hp2, wd0); fma2(f2a[2][1], hp2, wd1);
                fma2(f2a[3][0], hp3, wd0); fma2(f2a[3][1], hp3, wd1);
            }
            CP_WAIT0();
            __syncthreads();            // W1(kc+1) ready; XW/B2 reads complete
        }
        // write F2T into XT region (XW dead after final barrier)
        #pragma unroll
        for (int j = 0; j < 2; ++j)
            #pragma unroll
            for (int p = 0; p < 4; ++p)
                *(u64*)&XT[(fc0 + j) * 66 + ft0 + 2 * p] = f2a[p][j];
    }
    __syncthreads();

    // ---- 11. LN2 stats
    ln_stats(XT, s_mu, s_rs, tid);
    __syncthreads();

    // ---- 12. out = skip + LN2(ffn), scatter with reverse roll
    for (int idx = tid; idx < TOK * Cc; idx += BT) {
        int c = idx >> 6, t = idx & 63;
        float v = B3[c * 66 + t] +
                  (XT[c * 66 + t] - s_mu[t]) * s_rs[t] * ln2_g[c] + ln2_b[c];
        int py = (wh * WS + (t >> 3) + SHIFT) & 63;
        int px = (ww * WS + (t & 7) + SHIFT) & 63;
        out[((b * Cc + c) * Hh + py) * Ww + px] = v;
    }
}

// ---------------------------------------------------------------------------
extern "C" void kernel_launch(void* const* d_in, const int* in_sizes, int n_in,
                              void* d_out, int out_size)
{
    const float* x      = (const float*)d_in[0];
    const float* qkv_w  = (const float*)d_in[1];
    const float* qkv_b  = (const float*)d_in[2];
    const float* proj_w = (const float*)d_in[3];
    const float* proj_b = (const float*)d_in[4];
    const float* meta_w1= (const float*)d_in[5];
    const float* meta_b1= (const float*)d_in[6];
    const float* meta_w2= (const float*)d_in[7];
    const float* meta_b2= (const float*)d_in[8];
    const float* tau    = (const float*)d_in[9];
    const float* ln1_g  = (const float*)d_in[10];
    const float* ln1_b  = (const float*)d_in[11];
    const float* ln2_g  = (const float*)d_in[12];
    const float* ln2_b  = (const float*)d_in[13];
    const float* ffn_w1 = (const float*)d_in[14];
    const float* ffn_b1 = (const float*)d_in[15];
    const float* ffn_w2 = (const float*)d_in[16];
    const float* ffn_b2 = (const float*)d_in[17];
    float* out = (float*)d_out;

    const int smem = SM_FLOATS * sizeof(float);   // 203776 B
    cudaFuncSetAttribute(swin_block_kernel,
                         cudaFuncAttributeMaxDynamicSharedMemorySize, smem);

    bias_kernel<<<(TOK * TOK + 255) / 256, 256>>>(meta_w1, meta_b1, meta_w2, meta_b2);
    swin_block_kernel<<<Bq * NWIN, BT, smem>>>(
        x, qkv_w, qkv_b, proj_w, proj_b, tau,
        ln1_g, ln1_b, ln2_g, ln2_b,
        ffn_w1, ffn_b1, ffn_w2, ffn_b2, out);
}

// round 13
// speedup vs baseline: 1.5970x; 1.5970x over previous
#include <cuda_runtime.h>
#include <math.h>

typedef unsigned long long u64;

// Problem constants
#define Bq   32
#define Cc   128
#define Hh   64
#define Ww   64
#define WS   8
#define SHIFT 4
#define HEADS 4
#define HID  512
#define METAH 256
#define TOK  64
#define NWIN 64
#define DH   32

#define BT   512
#define SP   68          // padded row stride: 68*4B = 272B ≡ 0 mod 16

// smem layout (floats)
#define OFF_A   0        // XT [128][68]  -> W2 stage (XW) -> F2T
#define OFF_B1  8704     // QT [128][68]  -> AO
#define OFF_B2  17408    // KT [128][68]  -> PT -> HT
#define OFF_B3  26112    // VR [64][136]  -> ST [128][68]
#define OFF_S   34816    // weight stage (dbl-buf) / scores [4][64][68] = 17408
#define SM_FLOATS 52224  // total = 208896 bytes

__device__ float g_bias[HEADS * TOK * TOK];

// ---- packed f32x2 helpers --------------------------------------------------
__device__ __forceinline__ u64 pk(float lo, float hi) {
    u64 r; asm("mov.b64 %0,{%1,%2};" : "=l"(r) : "f"(lo), "f"(hi)); return r;
}
__device__ __forceinline__ void fma2(u64& d, u64 a, u64 b) {
    asm("fma.rn.f32x2 %0, %1, %2, %0;" : "+l"(d) : "l"(a), "l"(b));
}
__device__ __forceinline__ float2 upk(u64 v) {
    float2 f; asm("mov.b64 {%0,%1},%2;" : "=f"(f.x), "=f"(f.y) : "l"(v)); return f;
}
// one LDS.128 -> two packed f32x2 operands
__device__ __forceinline__ void ld4p(const float* p, u64& a, u64& b) {
    float4 v = *(const float4*)p;
    a = pk(v.x, v.y); b = pk(v.z, v.w);
}

// ---- cp.async helpers -------------------------------------------------------
__device__ __forceinline__ void cpa16(void* sptr, const void* gptr) {
    unsigned s = (unsigned)__cvta_generic_to_shared(sptr);
    asm volatile("cp.async.cg.shared.global [%0], [%1], 16;" :: "r"(s), "l"(gptr));
}
#define CP_COMMIT() asm volatile("cp.async.commit_group;" ::: "memory")
#define CP_WAIT0()  asm volatile("cp.async.wait_group 0;"  ::: "memory")

// ---------------------------------------------------------------------------
// Kernel A: meta-network relative position bias (identical for all windows)
// ---------------------------------------------------------------------------
__global__ void bias_kernel(const float* __restrict__ w1, const float* __restrict__ b1,
                            const float* __restrict__ w2, const float* __restrict__ b2)
{
    int p = blockIdx.x * blockDim.x + threadIdx.x;
    if (p >= TOK * TOK) return;
    int i = p >> 6, j = p & 63;
    float d0 = (float)((i >> 3) - (j >> 3));
    float d1 = (float)((i & 7) - (j & 7));
    float r0 = copysignf(log1pf(fabsf(d0)), d0);
    float r1 = copysignf(log1pf(fabsf(d1)), d1);
    float a0 = b2[0], a1 = b2[1], a2 = b2[2], a3 = b2[3];
    for (int m = 0; m < METAH; ++m) {
        float h = fmaf(r0, w1[m], fmaf(r1, w1[METAH + m], b1[m]));
        h = fmaxf(h, 0.0f);
        float4 wv = *reinterpret_cast<const float4*>(w2 + m * 4);
        a0 = fmaf(h, wv.x, a0); a1 = fmaf(h, wv.y, a1);
        a2 = fmaf(h, wv.z, a2); a3 = fmaf(h, wv.w, a3);
    }
    g_bias[0 * 4096 + p] = a0; g_bias[1 * 4096 + p] = a1;
    g_bias[2 * 4096 + p] = a2; g_bias[3 * 4096 + p] = a3;
}

__device__ __forceinline__ int regid(int y) {
    return (y < Hh - WS) ? 0 : ((y < Hh - SHIFT) ? 1 : 2);
}

// Parallel LN stats over a [128][SP] (feature-major) smem buffer.
__device__ __forceinline__ void ln_stats(const float* __restrict__ buf,
                                         float* __restrict__ s_mu,
                                         float* __restrict__ s_rs,
                                         int tid)
{
    int t = tid >> 3, l8 = tid & 7;
    float s = 0.f, s2 = 0.f;
    #pragma unroll
    for (int i = 0; i < 16; ++i) {
        float v = buf[(l8 + 8 * i) * SP + t];
        s += v;
        s2 = fmaf(v, v, s2);
    }
    #pragma unroll
    for (int m = 4; m >= 1; m >>= 1) {
        s  += __shfl_xor_sync(0xffffffffu, s,  m);
        s2 += __shfl_xor_sync(0xffffffffu, s2, m);
    }
    if (l8 == 0) {
        float mu = s * (1.0f / Cc);
        float var = fmaf(-mu, mu, s2 * (1.0f / Cc));
        s_mu[t] = mu;
        s_rs[t] = rsqrtf(var + 1e-5f);
    }
}

// ---------------------------------------------------------------------------
// Kernel B: fused Swin V2 block, one CTA per (batch, window)
// ---------------------------------------------------------------------------
__global__ void __launch_bounds__(BT, 1)
swin_block_kernel(const float* __restrict__ x,
                  const float* __restrict__ qkv_w, const float* __restrict__ qkv_b,
                  const float* __restrict__ proj_w, const float* __restrict__ proj_b,
                  const float* __restrict__ tau,
                  const float* __restrict__ ln1_g, const float* __restrict__ ln1_b,
                  const float* __restrict__ ln2_g, const float* __restrict__ ln2_b,
                  const float* __restrict__ ffn_w1, const float* __restrict__ ffn_b1,
                  const float* __restrict__ ffn_w2, const float* __restrict__ ffn_b2,
                  float* __restrict__ out)
{
    extern __shared__ float sm[];
    float* XT = sm + OFF_A;    // [c][t] stride SP ; later W2 stage, then F2T
    float* B1 = sm + OFF_B1;   // QT -> AO      [c][t] stride SP
    float* B2 = sm + OFF_B2;   // KT -> PT -> HT
    float* B3 = sm + OFF_B3;   // VR [k][c] stride 136 ; later ST [c][t] SP
    float* SS = sm + OFF_S;    // weight staging (dbl-buf) / scores S[h][ki][qi]

    __shared__ float s_qn[256], s_kn[256], s_mu[64], s_rs[64];

    const int tid = threadIdx.x;
    const int b  = blockIdx.x >> 6;
    const int wi = blockIdx.x & 63;
    const int wh = wi >> 3, ww = wi & 7;
    const float* xb = x + (size_t)b * Cc * Hh * Ww;

    float4* ssf4 = (float4*)SS;
    float4* xwf4 = (float4*)sm;                 // XT∪B1 region as flat stage
    const float4* qw4 = (const float4*)qkv_w;
    const float4* w14 = (const float4*)ffn_w1;
    const float4* w24 = (const float4*)ffn_w2;

    // ---- 1. gather shifted window, transposed: XT[c][t]
    for (int idx = tid; idx < TOK * Cc; idx += BT) {
        int c = idx >> 6, t = idx & 63;
        int py = (wh * WS + (t >> 3) + SHIFT) & 63;
        int px = (ww * WS + (t & 7) + SHIFT) & 63;
        XT[c * SP + t] = xb[c * 4096 + py * 64 + px];
    }

    // ---- 2. QKV GEMM: XT[64x128] @ W[128x384]
    // 8 chunks of 16 c-rows, cp.async double-buffered in the two SS halves.
    // j-map: thread jt owns channels {2jt, 2jt+1} in EACH of Q,K,V sections
    // -> all weight LDS.64 are lane-consecutive (conflict-free).
    {
        const int tt = tid >> 6, jt = tid & 63;
        const int t0 = tt * 8;
        u64 acc[4][6];   // [p][g*2+e]: g=0 Q, 1 K, 2 V
        #pragma unroll
        for (int g = 0; g < 3; ++g)
            #pragma unroll
            for (int e = 0; e < 2; ++e) {
                float bj = qkv_b[g * 128 + 2 * jt + e];
                u64 bd = pk(bj, bj);
                #pragma unroll
                for (int p = 0; p < 4; ++p) acc[p][g * 2 + e] = bd;
            }
        // issue chunk 0 into buffer 0
        for (int i = tid; i < 1536; i += BT) {
            int r = i / 96, q = i - r * 96;
            cpa16(ssf4 + i, qw4 + r * 96 + q);
        }
        CP_COMMIT();
        for (int ci = 0; ci < 8; ++ci) {
            int cur = ci & 1;
            CP_WAIT0();
            __syncthreads();            // chunk ci ready; (ci=0: also gather barrier)
            if (ci < 7) {               // stream chunk ci+1 into the other half
                float4* dst = ssf4 + (1 - cur) * 1536;
                int c1 = (ci + 1) * 16;
                for (int i = tid; i < 1536; i += BT) {
                    int r = i / 96, q = i - r * 96;
                    cpa16(dst + i, qw4 + (c1 + r) * 96 + q);
                }
                CP_COMMIT();
            }
            const float* Wb = SS + cur * 6144;
            const int c0 = ci * 16;
            for (int cc = 0; cc < 16; ++cc) {
                const float* xr = XT + (c0 + cc) * SP + t0;
                u64 xp0, xp1, xp2, xp3;
                ld4p(xr,     xp0, xp1);
                ld4p(xr + 4, xp2, xp3);
                const float* wr = Wb + cc * 384 + 2 * jt;
                float2 wq = *(const float2*)(wr);         // lane-consecutive
                float2 wk = *(const float2*)(wr + 128);
                float2 wv = *(const float2*)(wr + 256);
                u64 wd[6] = {pk(wq.x, wq.x), pk(wq.y, wq.y),
                             pk(wk.x, wk.x), pk(wk.y, wk.y),
                             pk(wv.x, wv.x), pk(wv.y, wv.y)};
                #pragma unroll
                for (int j = 0; j < 6; ++j) {
                    fma2(acc[0][j], xp0, wd[j]);
                    fma2(acc[1][j], xp1, wd[j]);
                    fma2(acc[2][j], xp2, wd[j]);
                    fma2(acc[3][j], xp3, wd[j]);
                }
            }
        }
        // write Q,K transposed [j][t]; V as [t][c] rows (for AV weight side)
        #pragma unroll
        for (int e = 0; e < 2; ++e) {
            int jc = 2 * jt + e;
            #pragma unroll
            for (int p = 0; p < 4; ++p) {
                *(u64*)&B1[jc * SP + t0 + 2 * p] = acc[p][e];       // Q
                *(u64*)&B2[jc * SP + t0 + 2 * p] = acc[p][2 + e];   // K
                float2 f = upk(acc[p][4 + e]);                       // V
                B3[(t0 + 2 * p)     * 136 + jc] = f.x;
                B3[(t0 + 2 * p + 1) * 136 + jc] = f.y;
            }
        }
    }
    __syncthreads();

    // ---- 3. q/k norms per (head, token); lane pair (tid, tid^1) splits DH
    {
        int r = tid >> 1, half = tid & 1;       // r = h*64 + t
        int h = r >> 6, t = r & 63;
        int d0 = half * 16;
        float sq = 0.f, sk = 0.f;
        #pragma unroll
        for (int d = 0; d < 16; ++d) {
            float qv = B1[(h * 32 + d0 + d) * SP + t];
            float kv = B2[(h * 32 + d0 + d) * SP + t];
            sq = fmaf(qv, qv, sq);
            sk = fmaf(kv, kv, sk);
        }
        sq += __shfl_xor_sync(0xffffffffu, sq, 1);
        sk += __shfl_xor_sync(0xffffffffu, sk, 1);
        if (half == 0) {
            s_qn[r] = sqrtf(sq);
            s_kn[r] = sqrtf(sk);
        }
    }
    __syncthreads();

    // ---- 4. scores -> SS as S[h][ki][qi] (stride SP)
    for (int it = tid; it < 1024; it += BT) {
        int h = it >> 8, qt = (it >> 4) & 15, kt = it & 15;
        int qi0 = qt * 4, ki0 = kt * 4;
        float tc = fmaxf(tau[h], 0.01f);
        float4 bq[4];
        #pragma unroll
        for (int p = 0; p < 4; ++p)
            bq[p] = *reinterpret_cast<const float4*>(
                        &g_bias[h * 4096 + (qi0 + p) * 64 + ki0]);
        u64 a0[4] = {0, 0, 0, 0}, a1[4] = {0, 0, 0, 0};
        for (int d = 0; d < DH; ++d) {
            int row = (h * 32 + d) * SP;
            u64 qp0, qp1;
            ld4p(&B1[row + qi0], qp0, qp1);
            float4 kv = *(const float4*)&B2[row + ki0];
            u64 kd0 = pk(kv.x, kv.x), kd1 = pk(kv.y, kv.y);
            u64 kd2 = pk(kv.z, kv.z), kd3 = pk(kv.w, kv.w);
            fma2(a0[0], qp0, kd0); fma2(a1[0], qp1, kd0);
            fma2(a0[1], qp0, kd1); fma2(a1[1], qp1, kd1);
            fma2(a0[2], qp0, kd2); fma2(a1[2], qp1, kd2);
            fma2(a0[3], qp0, kd3); fma2(a1[3], qp1, kd3);
        }
        int rq[4], rk[4];
        #pragma unroll
        for (int i = 0; i < 4; ++i) {
            int qi = qi0 + i, ki = ki0 + i;
            rq[i] = regid(wh * WS + (qi >> 3)) * 3 + regid(ww * WS + (qi & 7));
            rk[i] = regid(wh * WS + (ki >> 3)) * 3 + regid(ww * WS + (ki & 7));
        }
        #pragma unroll
        for (int j = 0; j < 4; ++j) {
            float knv = s_kn[h * 64 + ki0 + j];
            float2 v0 = upk(a0[j]), v1 = upk(a1[j]);
            float o[4] = {v0.x, v0.y, v1.x, v1.y};
            #pragma unroll
            for (int p = 0; p < 4; ++p) {
                int qi = qi0 + p;
                float bias = (j == 0) ? bq[p].x : (j == 1) ? bq[p].y
                           : (j == 2) ? bq[p].z : bq[p].w;
                float sc = o[p] / fmaxf(s_qn[h * 64 + qi] * knv * tc, 1e-6f * tc)
                         + bias;
                if (rq[p] != rk[j]) sc -= 100.0f;
                o[p] = sc;
            }
            *(u64*)&SS[h * 4352 + (ki0 + j) * SP + qi0]     = pk(o[0], o[1]);
            *(u64*)&SS[h * 4352 + (ki0 + j) * SP + qi0 + 2] = pk(o[2], o[3]);
        }
    }
    __syncthreads();

    // ---- 5. softmax per (h, qi); lane pair (tid, tid^1) splits the 64 ki's
    {
        int r = tid >> 1, half = tid & 1;       // r = h*64 + qi
        int h = r >> 6, qi = r & 63;
        float* base = SS + h * 4352 + qi + half * 32 * SP;
        float mx = -1e30f;
        #pragma unroll 8
        for (int k = 0; k < 32; ++k) mx = fmaxf(mx, base[k * SP]);
        mx = fmaxf(mx, __shfl_xor_sync(0xffffffffu, mx, 1));
        float ssum = 0.f;
        #pragma unroll 8
        for (int k = 0; k < 32; ++k) {
            float e = __expf(base[k * SP] - mx);
            base[k * SP] = e;
            ssum += e;
        }
        ssum += __shfl_xor_sync(0xffffffffu, ssum, 1);
        float inv = 1.0f / ssum;
        #pragma unroll 8
        for (int k = 0; k < 32; ++k) base[k * SP] *= inv;
    }
    __syncthreads();

    // ---- 6. AV: out[t][c] = sum_k S[h][k][t] * VR[k][c] -> AO[c][t] (B1)
    {
        int tt = tid >> 6, ct = tid & 63;
        int t0 = tt * 8, c0 = ct * 2, h = c0 >> 5;
        const float* Sh = SS + h * 4352;
        u64 av[4][2] = {{0,0},{0,0},{0,0},{0,0}};
        for (int k = 0; k < TOK; ++k) {
            const float* sr = Sh + k * SP + t0;
            u64 ap0, ap1, ap2, ap3;
            ld4p(sr,     ap0, ap1);
            ld4p(sr + 4, ap2, ap3);
            float2 v = *(const float2*)&B3[k * 136 + c0];
            u64 vd0 = pk(v.x, v.x), vd1 = pk(v.y, v.y);
            fma2(av[0][0], ap0, vd0); fma2(av[0][1], ap0, vd1);
            fma2(av[1][0], ap1, vd0); fma2(av[1][1], ap1, vd1);
            fma2(av[2][0], ap2, vd0); fma2(av[2][1], ap2, vd1);
            fma2(av[3][0], ap3, vd0); fma2(av[3][1], ap3, vd1);
        }
        #pragma unroll
        for (int j = 0; j < 2; ++j)
            #pragma unroll
            for (int p = 0; p < 4; ++p)
                *(u64*)&B1[(c0 + j) * SP + t0 + 2 * p] = av[p][j];
    }
    __syncthreads();

    // ---- 7. proj: AO @ proj_w -> PT[j][t] (B2); weights cp.async'd into SS
    {
        const float4* pw4 = (const float4*)proj_w;
        for (int i = tid; i < 4096; i += BT)
            cpa16(ssf4 + i, pw4 + i);
        CP_COMMIT(); CP_WAIT0();
    }
    __syncthreads();
    {
        int tt = tid >> 6, jt = tid & 63;
        int t0 = tt * 8, j0 = jt * 2;
        u64 pa[4][2];
        #pragma unroll
        for (int j = 0; j < 2; ++j) {
            float bj = proj_b[j0 + j];
            u64 bd = pk(bj, bj);
            #pragma unroll
            for (int p = 0; p < 4; ++p) pa[p][j] = bd;
        }
        for (int c = 0; c < Cc; ++c) {
            const float* xr = B1 + c * SP + t0;
            u64 xp0, xp1, xp2, xp3;
            ld4p(xr,     xp0, xp1);
            ld4p(xr + 4, xp2, xp3);
            float2 wp = *(const float2*)&SS[c * 128 + j0];   // lane-consecutive
            u64 wd0 = pk(wp.x, wp.x), wd1 = pk(wp.y, wp.y);
            fma2(pa[0][0], xp0, wd0); fma2(pa[0][1], xp0, wd1);
            fma2(pa[1][0], xp1, wd0); fma2(pa[1][1], xp1, wd1);
            fma2(pa[2][0], xp2, wd0); fma2(pa[2][1], xp2, wd1);
            fma2(pa[3][0], xp3, wd0); fma2(pa[3][1], xp3, wd1);
        }
        #pragma unroll
        for (int j = 0; j < 2; ++j)
            #pragma unroll
            for (int p = 0; p < 4; ++p)
                *(u64*)&B2[(j0 + j) * SP + t0 + 2 * p] = pa[p][j];
    }
    __syncthreads();

    // SS is dead now until FFN1 -> start streaming W1 chunk 0 (overlaps LN1/skip)
    for (int i = tid; i < 4096; i += BT) {
        int r = i >> 5, q = i & 31;
        cpa16(ssf4 + i, w14 + r * 128 + q);
    }
    CP_COMMIT();

    // ---- 8. LN1 stats (over channels of PT, per token)
    ln_stats(B2, s_mu, s_rs, tid);
    __syncthreads();

    // ---- 9. skip ST[c][t] = XT + LN1(PT) -> B3
    for (int idx = tid; idx < TOK * Cc; idx += BT) {
        int c = idx >> 6, t = idx & 63;
        float v = (B2[c * SP + t] - s_mu[t]) * s_rs[t] * ln1_g[c] + ln1_b[c];
        B3[c * SP + t] = v + XT[c * SP + t];
    }
    CP_WAIT0();
    __syncthreads();    // B3 ready AND W1(0) ready

    // ---- 10. FFN, hidden chunks of 128; FFN2 accs live in registers.
    // W2(kc) streams into XW (=XT∪B1, dead) during FFN1; W1(kc+1) into SS
    // during FFN2. 2 barriers per chunk.
    {
        int ftt = tid >> 6, fct = tid & 63;      // FFN2 tile: 8 t x 2 c
        int ft0 = ftt * 8, fc0 = fct * 2;
        u64 f2a[4][2];
        #pragma unroll
        for (int j = 0; j < 2; ++j) {
            float bb = ffn_b2[fc0 + j];
            u64 bd = pk(bb, bb);
            #pragma unroll
            for (int p = 0; p < 4; ++p) f2a[p][j] = bd;
        }
        int tt = tid >> 6, kt = tid & 63;
        int t0 = tt * 8, kk0 = kt * 2;

        for (int kc = 0; kc < 4; ++kc) {
            int k0 = kc * 128;
            // stream W2(kc) into XW while FFN1 computes
            for (int i = tid; i < 4096; i += BT) {
                int kk = i >> 5, q = i & 31;
                cpa16(xwf4 + i, w24 + (k0 + kk) * 32 + q);
            }
            CP_COMMIT();
            // FFN1: hidden = gelu(ST @ W1chunk + b1) -> HT[kk][t] (B2)
            u64 fa[4][2];
            #pragma unroll
            for (int j = 0; j < 2; ++j) {
                float bj = ffn_b1[k0 + kk0 + j];
                u64 bd = pk(bj, bj);
                #pragma unroll
                for (int p = 0; p < 4; ++p) fa[p][j] = bd;
            }
            for (int c = 0; c < Cc; ++c) {
                const float* xr = B3 + c * SP + t0;
                u64 xp0, xp1, xp2, xp3;
                ld4p(xr,     xp0, xp1);
                ld4p(xr + 4, xp2, xp3);
                float2 wp = *(const float2*)&SS[c * 128 + kk0];  // lane-consecutive
                u64 wd0 = pk(wp.x, wp.x), wd1 = pk(wp.y, wp.y);
                fma2(fa[0][0], xp0, wd0); fma2(fa[0][1], xp0, wd1);
                fma2(fa[1][0], xp1, wd0); fma2(fa[1][1], xp1, wd1);
                fma2(fa[2][0], xp2, wd0); fma2(fa[2][1], xp2, wd1);
                fma2(fa[3][0], xp3, wd0); fma2(fa[3][1], xp3, wd1);
            }
            // B2(HT) write: safe — FFN2(kc-1) reads of B2 ended before the
            // final barrier of the previous iteration.
            #pragma unroll
            for (int j = 0; j < 2; ++j)
                #pragma unroll
                for (int p = 0; p < 4; ++p) {
                    float2 v = upk(fa[p][j]);
                    float g0 = 0.5f * v.x * (1.0f + erff(v.x * 0.70710678118654752f));
                    float g1 = 0.5f * v.y * (1.0f + erff(v.y * 0.70710678118654752f));
                    *(u64*)&B2[(kk0 + j) * SP + t0 + 2 * p] = pk(g0, g1);
                }
            CP_WAIT0();
            __syncthreads();            // W2(kc) in XW + HT in B2 both ready
            // stream W1(kc+1) into SS while FFN2 computes (SS free: FFN1 done)
            if (kc < 3) {
                int k1 = (kc + 1) * 32;  // float4 col offset
                for (int i = tid; i < 4096; i += BT) {
                    int r = i >> 5, q = i & 31;
                    cpa16(ssf4 + i, w14 + r * 128 + k1 + q);
                }
                CP_COMMIT();
            }
            // FFN2 accumulate from XW (8 t x 2 c tile)
            for (int kk = 0; kk < 128; ++kk) {
                const float* hr = B2 + kk * SP + ft0;
                u64 hp0, hp1, hp2, hp3;
                ld4p(hr,     hp0, hp1);
                ld4p(hr + 4, hp2, hp3);
                float2 w = *(const float2*)&sm[kk * 128 + fc0];
                u64 wd0 = pk(w.x, w.x), wd1 = pk(w.y, w.y);
                fma2(f2a[0][0], hp0, wd0); fma2(f2a[0][1], hp0, wd1);
                fma2(f2a[1][0], hp1, wd0); fma2(f2a[1][1], hp1, wd1);
                fma2(f2a[2][0], hp2, wd0); fma2(f2a[2][1], hp2, wd1);
                fma2(f2a[3][0], hp3, wd0); fma2(f2a[3][1], hp3, wd1);
            }
            CP_WAIT0();
            __syncthreads();            // W1(kc+1) ready; XW/B2 reads complete
        }
        // write F2T into XT region (XW dead after final barrier)
        #pragma unroll
        for (int j = 0; j < 2; ++j)
            #pragma unroll
            for (int p = 0; p < 4; ++p)
                *(u64*)&XT[(fc0 + j) * SP + ft0 + 2 * p] = f2a[p][j];
    }
    __syncthreads();

    // ---- 11. LN2 stats
    ln_stats(XT, s_mu, s_rs, tid);
    __syncthreads();

    // ---- 12. out = skip + LN2(ffn), scatter with reverse roll
    for (int idx = tid; idx < TOK * Cc; idx += BT) {
        int c = idx >> 6, t = idx & 63;
        float v = B3[c * SP + t] +
                  (XT[c * SP + t] - s_mu[t]) * s_rs[t] * ln2_g[c] + ln2_b[c];
        int py = (wh * WS + (t >> 3) + SHIFT) & 63;
        int px = (ww * WS + (t & 7) + SHIFT) & 63;
        out[((b * Cc + c) * Hh + py) * Ww + px] = v;
    }
}

// ---------------------------------------------------------------------------
extern "C" void kernel_launch(void* const* d_in, const int* in_sizes, int n_in,
                              void* d_out, int out_size)
{
    const float* x      = (const float*)d_in[0];
    const float* qkv_w  = (const float*)d_in[1];
    const float* qkv_b  = (const float*)d_in[2];
    const float* proj_w = (const float*)d_in[3];
    const float* proj_b = (const float*)d_in[4];
    const float* meta_w1= (const float*)d_in[5];
    const float* meta_b1= (const float*)d_in[6];
    const float* meta_w2= (const float*)d_in[7];
    const float* meta_b2= (const float*)d_in[8];
    const float* tau    = (const float*)d_in[9];
    const float* ln1_g  = (const float*)d_in[10];
    const float* ln1_b  = (const float*)d_in[11];
    const float* ln2_g  = (const float*)d_in[12];
    const float* ln2_b  = (const float*)d_in[13];
    const float* ffn_w1 = (const float*)d_in[14];
    const float* ffn_b1 = (const float*)d_in[15];
    const float* ffn_w2 = (const float*)d_in[16];
    const float* ffn_b2 = (const float*)d_in[17];
    float* out = (float*)d_out;

    const int smem = SM_FLOATS * sizeof(float);   // 208896 B
    cudaFuncSetAttribute(swin_block_kernel,
                         cudaFuncAttributeMaxDynamicSharedMemorySize, smem);

    bias_kernel<<<(TOK * TOK + 255) / 256, 256>>>(meta_w1, meta_b1, meta_w2, meta_b2);
    swin_block_kernel<<<Bq * NWIN, BT, smem>>>(
        x, qkv_w, qkv_b, proj_w, proj_b, tau,
        ln1_g, ln1_b, ln2_g, ln2_b,
        ffn_w1, ffn_b1, ffn_w2, ffn_b2, out);
}